// round 9
// baseline (speedup 1.0000x reference)
#include <cuda_runtime.h>
#include <cuda_fp16.h>

__device__ __forceinline__ unsigned int h2u(__half2 h) {
    unsigned int u; memcpy(&u, &h, 4); return u;
}
__device__ __forceinline__ __half2 u2h(unsigned int u) {
    __half2 h; memcpy(&h, &u, 4); return h;
}
__device__ __forceinline__ __half2 tanh_h2(__half2 v) {
    unsigned int r;
    asm("tanh.approx.f16x2 %0, %1;" : "=r"(r) : "r"(h2u(v)));
    return u2h(r);
}
// sigmoid on half2: 0.5 + 0.5*tanh(0.5*x), one MUFU per 2 values
__device__ __forceinline__ __half2 sigmoid_h2(__half2 v) {
    const __half2 half_ = __float2half2_rn(0.5f);
    return __hfma2(half_, tanh_h2(__hmul2(half_, v)), half_);
}

// D[16,8] = A[16,8]*B[8,8], f16; D-frag layout == A-frag layout -> layers chain.
__device__ __forceinline__ void mma8_f16(unsigned int& d0, unsigned int& d1,
                                         unsigned int a0, unsigned int a1,
                                         unsigned int b) {
    unsigned int r0, r1;
    asm("mma.sync.aligned.m16n8k8.row.col.f16.f16.f16.f16 "
        "{%0,%1}, {%2,%3}, {%4}, {%5,%6};"
        : "=r"(r0), "=r"(r1)
        : "r"(a0), "r"(a1), "r"(b), "r"(0u), "r"(0u));
    d0 = r0; d1 = r1;
}

#define TILP 4

// Heterogeneous warp specialization: warps 0-3 of each block run the HFMA2
// (fma-pipe) path; warps 4-7 run the mma (tensor-pipe) path. The two paths
// saturate disjoint pipes (fma vs tensor/MUFU) and share issue slots.
__global__ void __launch_bounds__(256, 2)
mlp_hybrid_kernel(const float* __restrict__ x,
                  const float* __restrict__ W_in,
                  const float* __restrict__ W_h,
                  const float* __restrict__ W_out,
                  float* __restrict__ out,
                  int npairsF,   // pairs handled by HFMA2 warps (pixels [0, 2*npairsF))
                  int ntilesT,   // 16-pixel tiles handled by mma warps
                  int pxBaseT)   // first pixel of the mma region (= 2*npairsF)
{
    const int wid  = threadIdx.x >> 5;
    const int lane = threadIdx.x & 31;

    if (wid < 4) {
        // ================= F path: HFMA2, one pixel-pair per lane =================
        const int fwid = blockIdx.x * 4 + wid;
        const int nF = gridDim.x * 4;
        const float4* x4 = (const float4*)x;
        float2* out2 = (float2*)out;

        __half2 winx[8], winy[8];
#pragma unroll
        for (int j = 0; j < 8; j++) {
            winx[j] = __float2half2_rn(__ldg(W_in + 2 * j));
            winy[j] = __float2half2_rn(__ldg(W_in + 2 * j + 1));
        }
        __half2 wh[64];
#pragma unroll
        for (int i = 0; i < 64; i++) wh[i] = __float2half2_rn(__ldg(W_h + i));
        __half2 wout[24];
#pragma unroll
        for (int i = 0; i < 24; i++) wout[i] = __float2half2_rn(__ldg(W_out + i));

        for (int p = fwid * 32 + lane; p < npairsF; p += nF * 32) {
            float4 xy = __ldg(x4 + p);  // (x0,y0,x1,y1)
            __half2 xv = __floats2half2_rn(xy.x, xy.z);
            __half2 yv = __floats2half2_rn(xy.y, xy.w);

            __half2 h[8];
#pragma unroll
            for (int j = 0; j < 8; j++)
                h[j] = tanh_h2(__hfma2(winy[j], yv, __hmul2(winx[j], xv)));

#pragma unroll
            for (int l = 0; l < 4; l++) {
                __half2 nh[8];
#pragma unroll
                for (int j = 0; j < 8; j++) {
                    __half2 acc = __hmul2(wh[8 * j + 0], h[0]);
#pragma unroll
                    for (int k = 1; k < 8; k++)
                        acc = __hfma2(wh[8 * j + k], h[k], acc);
                    nh[j] = tanh_h2(acc);
                }
#pragma unroll
                for (int j = 0; j < 8; j++) h[j] = nh[j];
            }

            // output layer + f16x2 sigmoid (3 MUFU instead of 6)
            float2 s[3];
#pragma unroll
            for (int o = 0; o < 3; o++) {
                __half2 acc = __hmul2(wout[8 * o + 0], h[0]);
#pragma unroll
                for (int k = 1; k < 8; k++)
                    acc = __hfma2(wout[8 * o + k], h[k], acc);
                s[o] = __half22float2(sigmoid_h2(acc));
            }
            // pair p occupies floats [6p, 6p+6) = float2 slots [3p, 3p+3), 8B-aligned
            float2* dst = out2 + 3ll * p;
            dst[0] = make_float2(s[0].x, s[1].x);
            dst[1] = make_float2(s[2].x, s[0].y);
            dst[2] = make_float2(s[1].y, s[2].y);
        }
    } else {
        // ================= T path: mma, 16 pixels per tile, ILP=4 =================
        const int twid = blockIdx.x * 4 + (wid - 4);
        const int nT = gridDim.x * 4;
        const int g = lane >> 2;   // 0..7
        const int c = lane & 3;    // 0..3
        const float2* x2 = (const float2*)x;

        unsigned int b_in = (c == 0)
            ? h2u(__floats2half2_rn(__ldg(W_in + 2 * g), __ldg(W_in + 2 * g + 1)))
            : 0u;
        unsigned int b_h =
            h2u(__floats2half2_rn(__ldg(W_h + 8 * g + 2 * c), __ldg(W_h + 8 * g + 2 * c + 1)));
        unsigned int b_out = (g < 3)
            ? h2u(__floats2half2_rn(__ldg(W_out + 8 * g + 2 * c), __ldg(W_out + 8 * g + 2 * c + 1)))
            : 0u;

        for (int t0 = twid * TILP; t0 < ntilesT; t0 += nT * TILP) {
            unsigned int h0[TILP], h1[TILP];
            int nu = min(TILP, ntilesT - t0);

#pragma unroll
            for (int u = 0; u < TILP; u++) {
                if (u >= nu) break;
                int base = pxBaseT + (t0 + u) * 16;
                float2 p0 = __ldg(x2 + base + g);
                float2 p1 = __ldg(x2 + base + 8 + g);
                unsigned int a0 = (c == 0) ? h2u(__floats2half2_rn(p0.x, p0.y)) : 0u;
                unsigned int a1 = (c == 0) ? h2u(__floats2half2_rn(p1.x, p1.y)) : 0u;
                unsigned int d0, d1;
                mma8_f16(d0, d1, a0, a1, b_in);
                h0[u] = h2u(tanh_h2(u2h(d0)));
                h1[u] = h2u(tanh_h2(u2h(d1)));
            }

#pragma unroll
            for (int l = 0; l < 4; l++) {
#pragma unroll
                for (int u = 0; u < TILP; u++) {
                    if (u >= nu) break;
                    unsigned int d0, d1;
                    mma8_f16(d0, d1, h0[u], h1[u], b_h);
                    h0[u] = h2u(tanh_h2(u2h(d0)));
                    h1[u] = h2u(tanh_h2(u2h(d1)));
                }
            }

#pragma unroll
            for (int u = 0; u < TILP; u++) {
                if (u >= nu) break;
                unsigned int d0, d1;
                mma8_f16(d0, d1, h0[u], h1[u], b_out);
                // d0 = {out[g][2c], out[g][2c+1]}, d1 = same for row g+8
                float2 s0 = __half22float2(sigmoid_h2(u2h(d0)));
                float2 s1 = __half22float2(sigmoid_h2(u2h(d1)));
                int base = pxBaseT + (t0 + u) * 16;
                long long r0 = base + g;
                long long r1 = base + 8 + g;
                // scalar stores: out rows are 3 floats (12B) -> never 8B-aligned
                if (c == 0) {
                    out[r0 * 3 + 0] = s0.x;
                    out[r0 * 3 + 1] = s0.y;
                    out[r1 * 3 + 0] = s1.x;
                    out[r1 * 3 + 1] = s1.y;
                } else if (c == 1) {
                    out[r0 * 3 + 2] = s0.x;
                    out[r1 * 3 + 2] = s1.x;
                }
            }
        }
    }
}

extern "C" void kernel_launch(void* const* d_in, const int* in_sizes, int n_in,
                              void* d_out, int out_size)
{
    const float* x     = (const float*)d_in[0];  // [N, 2]
    const float* W_in  = (const float*)d_in[1];  // [8, 2]
    const float* W_h   = (const float*)d_in[2];  // [8, 8]
    const float* W_out = (const float*)d_in[3];  // [3, 8]

    int n_pixels = in_sizes[0] / 2;              // 16777216
    // Split: 7/16 of pixels to the HFMA2 warps, 9/16 to the mma warps.
    long long pxF = ((long long)n_pixels * 7 / 16) & ~31LL;  // multiple of 32
    int npairsF = (int)(pxF / 2);
    int pxBaseT = (int)pxF;
    int ntilesT = (n_pixels - pxBaseT) / 16;

    const int threads = 256;
    const int blocks = 912;  // 3 waves at 2 blocks/SM -> fine-grained tail
    mlp_hybrid_kernel<<<blocks, threads>>>(x, W_in, W_h, W_out, (float*)d_out,
                                           npairsF, ntilesT, pxBaseT);
}

// round 10
// speedup vs baseline: 2.2352x; 2.2352x over previous
#include <cuda_runtime.h>
#include <cuda_fp16.h>
#include <cmath>

// ---------------- packed f32x2 helpers (Blackwell) ----------------
__device__ __forceinline__ unsigned long long pack2(float lo, float hi) {
    unsigned long long r;
    asm("mov.b64 %0, {%1, %2};" : "=l"(r) : "f"(lo), "f"(hi));
    return r;
}
__device__ __forceinline__ void unpack2(unsigned long long v, float& lo, float& hi) {
    asm("mov.b64 {%0, %1}, %2;" : "=f"(lo), "=f"(hi) : "l"(v));
}
__device__ __forceinline__ unsigned long long fma2(unsigned long long a,
                                                   unsigned long long b,
                                                   unsigned long long c) {
    unsigned long long d;
    asm("fma.rn.f32x2 %0, %1, %2, %3;" : "=l"(d) : "l"(a), "l"(b), "l"(c));
    return d;
}
__device__ __forceinline__ unsigned long long mul2(unsigned long long a,
                                                   unsigned long long b) {
    unsigned long long d;
    asm("mul.rn.f32x2 %0, %1, %2;" : "=l"(d) : "l"(a), "l"(b));
    return d;
}

// ---------------- half2 / MUFU helpers ----------------
__device__ __forceinline__ unsigned int h2u(__half2 h) {
    unsigned int u; memcpy(&u, &h, 4); return u;
}
__device__ __forceinline__ unsigned int tanh_h2u(unsigned int x) {
    unsigned int r;
    asm("tanh.approx.f16x2 %0, %1;" : "=r"(r) : "r"(x));
    return r;
}
__device__ __forceinline__ float tanh_f32(float x) {
    float y;
    asm("tanh.approx.f32 %0, %1;" : "=f"(y) : "f"(x));
    return y;
}
__device__ __forceinline__ float sigmoid_fast(float x) {
    return fmaf(0.5f, tanh_f32(0.5f * x), 0.5f);
}
// pack two f32 into f16x2: lo half <- lo, hi half <- hi
__device__ __forceinline__ unsigned int f2h2(float hi, float lo) {
    unsigned int r;
    asm("cvt.rn.f16x2.f32 %0, %1, %2;" : "=r"(r) : "f"(hi), "f"(lo));
    return r;
}

// ---------------- mma: D[16,8] = A[16,8]*B[8,8] ----------------
__device__ __forceinline__ void mma8_f16(unsigned int& d0, unsigned int& d1,
                                         unsigned int a0, unsigned int a1,
                                         unsigned int b) {
    unsigned int r0, r1;
    asm("mma.sync.aligned.m16n8k8.row.col.f16.f16.f16.f16 "
        "{%0,%1}, {%2,%3}, {%4}, {%5,%6};"
        : "=r"(r0), "=r"(r1)
        : "r"(a0), "r"(a1), "r"(b), "r"(0u), "r"(0u));
    d0 = r0; d1 = r1;
}
__device__ __forceinline__ void mma8_f32(float& d0, float& d1, float& d2, float& d3,
                                         unsigned int a0, unsigned int a1,
                                         unsigned int b) {
    asm("mma.sync.aligned.m16n8k8.row.col.f32.f16.f16.f32 "
        "{%0,%1,%2,%3}, {%4,%5}, {%6}, {%7,%8,%9,%10};"
        : "=f"(d0), "=f"(d1), "=f"(d2), "=f"(d3)
        : "r"(a0), "r"(a1), "r"(b),
          "f"(0.0f), "f"(0.0f), "f"(0.0f), "f"(0.0f));
}

// tanh poly coefficients (fitted on host at launch): tanh(x) ~= x * P(u),
// u = (x/xmax)^2, P = c0 + c1 u + ... + c6 u^6, valid after clamp |x|<=xmax.
struct PolyC {
    float c0, c1, c2, c3, c4, c5, c6;
    float inv_xmax2;   // 1/xmax^2
    float xmax;
};

#define TILP 4

__global__ void __launch_bounds__(256)
mlp_mma_poly_kernel(const float2* __restrict__ x2,
                    const float* __restrict__ W_in,
                    const float* __restrict__ W_h,
                    const float* __restrict__ W_out,
                    float* __restrict__ out,
                    int ntiles, PolyC pc)
{
    const int lane = threadIdx.x & 31;
    const int g = lane >> 2;   // 0..7
    const int c = lane & 3;    // 0..3
    const int warp = (blockIdx.x * blockDim.x + threadIdx.x) >> 5;
    const int nwarps = (gridDim.x * blockDim.x) >> 5;

    // B fragments: b = {W[g][2c], W[g][2c+1]}
    unsigned int b_in = (c == 0)
        ? h2u(__floats2half2_rn(__ldg(W_in + 2 * g), __ldg(W_in + 2 * g + 1)))
        : 0u;
    unsigned int b_h =
        h2u(__floats2half2_rn(__ldg(W_h + 8 * g + 2 * c), __ldg(W_h + 8 * g + 2 * c + 1)));
    unsigned int b_out = (g < 3)
        ? h2u(__floats2half2_rn(__ldg(W_out + 8 * g + 2 * c), __ldg(W_out + 8 * g + 2 * c + 1)))
        : 0u;

    // duplicated-packed poly coefficients (f32x2)
    const unsigned long long C0 = pack2(pc.c0, pc.c0);
    const unsigned long long C1 = pack2(pc.c1, pc.c1);
    const unsigned long long C2 = pack2(pc.c2, pc.c2);
    const unsigned long long C3 = pack2(pc.c3, pc.c3);
    const unsigned long long C4 = pack2(pc.c4, pc.c4);
    const unsigned long long C5 = pack2(pc.c5, pc.c5);
    const unsigned long long C6 = pack2(pc.c6, pc.c6);
    const unsigned long long INV = pack2(pc.inv_xmax2, pc.inv_xmax2);
    const float xmax = pc.xmax;

    for (int t0 = warp * TILP; t0 < ntiles; t0 += nwarps * TILP) {
        unsigned int h0[TILP], h1[TILP];

        // ---- input layer: f16 mma + MUFU tanh ----
#pragma unroll
        for (int u = 0; u < TILP; u++) {
            int base = (t0 + u) * 16;
            float2 p0 = __ldg(x2 + base + g);
            float2 p1 = __ldg(x2 + base + 8 + g);
            unsigned int a0 = (c == 0) ? h2u(__floats2half2_rn(p0.x, p0.y)) : 0u;
            unsigned int a1 = (c == 0) ? h2u(__floats2half2_rn(p1.x, p1.y)) : 0u;
            unsigned int d0, d1;
            mma8_f16(d0, d1, a0, a1, b_in);
            h0[u] = tanh_h2u(d0);
            h1[u] = tanh_h2u(d1);
        }

        // ---- 4 hidden layers: alternate poly(fma pipe) / MUFU ----
#pragma unroll
        for (int l = 0; l < 4; l++) {
            if ((l & 1) == 0) {
                // POLY layer: f32-accum mma, clamp, packed-f32x2 Horner, cvt back
#pragma unroll
                for (int u = 0; u < TILP; u++) {
                    float d0, d1, d2, d3;
                    mma8_f32(d0, d1, d2, d3, h0[u], h1[u], b_h);
                    d0 = fminf(fmaxf(d0, -xmax), xmax);
                    d1 = fminf(fmaxf(d1, -xmax), xmax);
                    d2 = fminf(fmaxf(d2, -xmax), xmax);
                    d3 = fminf(fmaxf(d3, -xmax), xmax);
                    unsigned long long vA = pack2(d0, d1);
                    unsigned long long vB = pack2(d2, d3);
                    unsigned long long uA = mul2(mul2(vA, vA), INV);
                    unsigned long long uB = mul2(mul2(vB, vB), INV);
                    unsigned long long pA = fma2(C6, uA, C5);
                    unsigned long long pB = fma2(C6, uB, C5);
                    pA = fma2(pA, uA, C4);  pB = fma2(pB, uB, C4);
                    pA = fma2(pA, uA, C3);  pB = fma2(pB, uB, C3);
                    pA = fma2(pA, uA, C2);  pB = fma2(pB, uB, C2);
                    pA = fma2(pA, uA, C1);  pB = fma2(pB, uB, C1);
                    pA = fma2(pA, uA, C0);  pB = fma2(pB, uB, C0);
                    unsigned long long rA = mul2(pA, vA);
                    unsigned long long rB = mul2(pB, vB);
                    float r0, r1, r2, r3;
                    unpack2(rA, r0, r1);
                    unpack2(rB, r2, r3);
                    h0[u] = f2h2(r1, r0);   // hi=col 2c+1, lo=col 2c
                    h1[u] = f2h2(r3, r2);
                }
            } else {
                // MUFU layer: f16-accum mma + tanh.approx.f16x2
#pragma unroll
                for (int u = 0; u < TILP; u++) {
                    unsigned int d0, d1;
                    mma8_f16(d0, d1, h0[u], h1[u], b_h);
                    h0[u] = tanh_h2u(d0);
                    h1[u] = tanh_h2u(d1);
                }
            }
        }

        // ---- output layer: f32-accum mma + f32 sigmoid + scalar stores ----
#pragma unroll
        for (int u = 0; u < TILP; u++) {
            float d0, d1, d2, d3;
            mma8_f32(d0, d1, d2, d3, h0[u], h1[u], b_out);
            int base = (t0 + u) * 16;
            if (c < 2) {
                float s0 = sigmoid_fast(d0);
                float s1 = sigmoid_fast(d1);
                float s2 = sigmoid_fast(d2);
                float s3 = sigmoid_fast(d3);
                long long r0 = base + g;
                long long r1 = base + 8 + g;
                if (c == 0) {
                    out[r0 * 3 + 0] = s0;
                    out[r0 * 3 + 1] = s1;
                    out[r1 * 3 + 0] = s2;
                    out[r1 * 3 + 1] = s3;
                } else {
                    out[r0 * 3 + 2] = s0;
                    out[r1 * 3 + 2] = s2;
                }
            }
        }
    }
}

// ---------------- host: weighted LS fit of tanh(x)/x on [0, xmax] ----------------
static void fit_tanh_poly(double xmax, float* cf /*7*/) {
    const int NS = 4000;
    double ATA[7][7] = {{0}}, ATy[7] = {0};
    for (int j = 1; j <= NS; j++) {
        double x = xmax * j / NS;
        double u = (x / xmax) * (x / xmax);
        double y = tanh(x) / x;
        double w2 = x * x;  // weight^2 = x^2 -> minimizes abs tanh error in L2
        double pu[7];
        pu[0] = 1.0;
        for (int i = 1; i < 7; i++) pu[i] = pu[i - 1] * u;
        for (int a = 0; a < 7; a++) {
            for (int b = 0; b < 7; b++) ATA[a][b] += w2 * pu[a] * pu[b];
            ATy[a] += w2 * pu[a] * y;
        }
    }
    // Gaussian elimination with partial pivoting
    for (int k = 0; k < 7; k++) {
        int piv = k;
        for (int r = k + 1; r < 7; r++)
            if (fabs(ATA[r][k]) > fabs(ATA[piv][k])) piv = r;
        if (piv != k) {
            for (int cidx = 0; cidx < 7; cidx++) {
                double t = ATA[k][cidx]; ATA[k][cidx] = ATA[piv][cidx]; ATA[piv][cidx] = t;
            }
            double t = ATy[k]; ATy[k] = ATy[piv]; ATy[piv] = t;
        }
        for (int r = k + 1; r < 7; r++) {
            double f = ATA[r][k] / ATA[k][k];
            for (int cidx = k; cidx < 7; cidx++) ATA[r][cidx] -= f * ATA[k][cidx];
            ATy[r] -= f * ATy[k];
        }
    }
    double sol[7];
    for (int k = 6; k >= 0; k--) {
        double s = ATy[k];
        for (int cidx = k + 1; cidx < 7; cidx++) s -= ATA[k][cidx] * sol[cidx];
        sol[k] = s / ATA[k][k];
    }
    for (int i = 0; i < 7; i++) cf[i] = (float)sol[i];
}

extern "C" void kernel_launch(void* const* d_in, const int* in_sizes, int n_in,
                              void* d_out, int out_size)
{
    const float* x     = (const float*)d_in[0];  // [N, 2]
    const float* W_in  = (const float*)d_in[1];  // [8, 2]
    const float* W_h   = (const float*)d_in[2];  // [8, 8]
    const float* W_out = (const float*)d_in[3];  // [3, 8]

    int n_pixels = in_sizes[0] / 2;      // 16777216
    int ntiles = n_pixels / 16;          // 1048576, divisible by TILP

    const double XMAX = 3.2;
    PolyC pc;
    float cf[7];
    fit_tanh_poly(XMAX, cf);
    pc.c0 = cf[0]; pc.c1 = cf[1]; pc.c2 = cf[2]; pc.c3 = cf[3];
    pc.c4 = cf[4]; pc.c5 = cf[5]; pc.c6 = cf[6];
    pc.inv_xmax2 = (float)(1.0 / (XMAX * XMAX));
    pc.xmax = (float)XMAX;

    const int threads = 256;
    const int blocks = 1216;
    mlp_mma_poly_kernel<<<blocks, threads>>>((const float2*)x, W_in, W_h, W_out,
                                             (float*)d_out, ntiles, pc);
}